// round 6
// baseline (speedup 1.0000x reference)
#include <cuda_runtime.h>
#include <cuda_bf16.h>
#include <cstdint>

#define IN_C  64
#define OUT_C 64
#define HH    112
#define WW    112
#define NB    2

#define TROWS 4
#define TCOLS 16
#define KTOT  576
#define KCH   64
#define NCHUNK 9

// raw tile: 64 ic x 6 rows x 18 cols (packed hi|lo uint32)
#define RAW_R 6
#define RAW_C 18
#define RAW_PER_IC (RAW_R * RAW_C)      // 108
#define RAW_ELEMS  (IN_C * RAW_PER_IC)  // 6912

#define APAD 72          // bf16 elems per row (144 B)
#define ROWB (APAD * 2)  // 144 bytes per row

// tile buffer layout (per stage, 36864 B): AH 0 | AL 9216 | BH 18432 | BL 27648
#define STAGE_BYTES 36864u
#define OFF_AH  0u
#define OFF_AL  9216u
#define OFF_BH  18432u
#define OFF_BL  27648u
// after 2 stages:
#define OFF_RAW 73728u      // 27648 B (uint32 packed)
#define OFF_LUT 101376u     // 2304 B
#define OFF_BIAS 103680u    // 256 B
#define SMEM_BYTES 103936u

// pre-converted weights: [chunk 9][n 64][k 64] bf16
__device__ __align__(16) __nv_bfloat16 Bh_g[NCHUNK * 64 * KCH];
__device__ __align__(16) __nv_bfloat16 Bl_g[NCHUNK * 64 * KCH];

__device__ __forceinline__ uint32_t smem_u32(const void* p) {
    uint32_t a;
    asm("{ .reg .u64 t; cvta.to.shared.u64 t, %1; cvt.u32.u64 %0, t; }" : "=r"(a) : "l"(p));
    return a;
}

__device__ __forceinline__ void mma_bf16(float* d, const uint32_t* a, const uint32_t* b) {
    asm volatile(
        "mma.sync.aligned.m16n8k16.row.col.f32.bf16.bf16.f32 "
        "{%0,%1,%2,%3}, {%4,%5,%6,%7}, {%8,%9}, {%0,%1,%2,%3};"
        : "+f"(d[0]), "+f"(d[1]), "+f"(d[2]), "+f"(d[3])
        : "r"(a[0]), "r"(a[1]), "r"(a[2]), "r"(a[3]), "r"(b[0]), "r"(b[1]));
}

__device__ __forceinline__ void ldmx4(uint32_t* r, uint32_t addr) {
    asm volatile("ldmatrix.sync.aligned.m8n8.x4.shared.b16 {%0,%1,%2,%3}, [%4];"
        : "=r"(r[0]), "=r"(r[1]), "=r"(r[2]), "=r"(r[3]) : "r"(addr));
}

__device__ __forceinline__ uint32_t prmt(uint32_t a, uint32_t b, uint32_t sel) {
    uint32_t d;
    asm("prmt.b32 %0, %1, %2, %3;" : "=r"(d) : "r"(a), "r"(b), "r"(sel));
    return d;
}

// ---- pre-kernel: split weights to bf16 hi/lo, chunked layout ----
__global__ void __launch_bounds__(256)
prep_weights_kernel(const float* __restrict__ wgt)
{
    const int i = blockIdx.x * 256 + threadIdx.x;
    if (i >= NCHUNK * 64 * KCH) return;
    const int chunk = i >> 12;
    const int rem   = i & 4095;
    const int n     = rem >> 6;
    const int kk    = rem & 63;
    const float v = wgt[n * KTOT + chunk * KCH + kk];
    // truncation hi (matches main-kernel A split), rn lo
    const uint32_t u  = __float_as_uint(v);
    const uint32_t hu = u & 0xFFFF0000u;
    const float lo = v - __uint_as_float(hu);
    Bh_g[i] = __ushort_as_bfloat16((unsigned short)(hu >> 16));
    Bl_g[i] = __float2bfloat16_rn(lo);
}

// ---- main kernel ----
__global__ void __launch_bounds__(256, 2)
conv3x3_hmma_kernel(const float* __restrict__ x,
                    const float* __restrict__ bias,
                    float* __restrict__ out)
{
    extern __shared__ char sm[];
    const uint32_t sb = smem_u32(sm);

    const int tid  = threadIdx.x;
    const int wid  = tid >> 5;
    const int lane = tid & 31;
    const int grp  = lane >> 2;
    const int tid4 = lane & 3;

    const int wm = wid & 3;         // warp m-group (4 x 16 rows)
    const int wn = wid >> 2;        // warp n-group (2 x 32 cols)

    const int col0 = blockIdx.x * TCOLS;
    const int row0 = blockIdx.y * TROWS;
    const int b    = blockIdx.z;

    uint32_t* rawp  = (uint32_t*)(sm + OFF_RAW);
    int*      lut   = (int*)(sm + OFF_LUT);
    float*    biass = (float*)(sm + OFF_BIAS);

    // ---- stage raw x tile, pre-split into packed (hi16|lo16) ----
    for (int e = tid; e < RAW_ELEMS; e += 256) {
        const int ic  = e / RAW_PER_IC;
        const int rem = e - ic * RAW_PER_IC;
        const int r   = rem / RAW_C;
        const int c   = rem - r * RAW_C;
        const int gr  = row0 - 1 + r;
        const int gc  = col0 - 1 + c;
        float v = 0.0f;
        if ((unsigned)gr < (unsigned)HH && (unsigned)gc < (unsigned)WW)
            v = x[(((b * IN_C) + ic) * HH + gr) * WW + gc];
        const uint32_t u  = __float_as_uint(v);
        const uint32_t hu = u & 0xFFFF0000u;
        const float lo = v - __uint_as_float(hu);
        rawp[e] = hu | (uint32_t)__bfloat16_as_ushort(__float2bfloat16_rn(lo));
    }
    for (int e = tid; e < KTOT; e += 256) {
        const int ic  = e / 9;
        const int tap = e - ic * 9;
        const int dy  = tap / 3;
        const int dx  = tap - dy * 3;
        lut[e] = ic * RAW_PER_IC + dy * RAW_C + dx;
    }
    if (tid < OUT_C) biass[tid] = bias[tid];

    float acc[4][4];
    #pragma unroll
    for (int g = 0; g < 4; ++g)
        #pragma unroll
        for (int q = 0; q < 4; ++q) acc[g][q] = 0.0f;

    // A build mapping
    const int mg = tid >> 3;        // 0..31
    const int u8 = tid & 7;         // 0..7

    // ---- ldmatrix per-lane base addresses (within a stage) ----
    const int matq = lane >> 3;
    const int rq   = lane & 7;
    const uint32_t aA = sb
        + (uint32_t)(wm * 16 + ((matq & 1) << 3) + rq) * ROWB
        + (uint32_t)((matq >> 1) << 4);
    const uint32_t aB = sb + OFF_BH
        + (uint32_t)(wn * 32 + ((matq >> 1) << 3) + rq) * ROWB
        + (uint32_t)((matq & 1) << 4);

    // pipeline registers
    uint32_t av[2][8];
    uint4 bhv[2], blv[2];

    // ---- gather chunk data into registers ----
    auto gather = [&](int chunk) {
        int o[8];
        #pragma unroll
        for (int t = 0; t < 8; ++t) o[t] = lut[chunk * KCH + u8 * 8 + t];
        #pragma unroll
        for (int j = 0; j < 2; ++j) {
            const int m    = j * 32 + mg;
            const int base = (m >> 4) * RAW_C + (m & 15);
            #pragma unroll
            for (int t = 0; t < 8; ++t) av[j][t] = rawp[base + o[t]];
        }
        const uint4* bsh = ((const uint4*)Bh_g) + chunk * 512;
        const uint4* bsl = ((const uint4*)Bl_g) + chunk * 512;
        bhv[0] = bsh[tid]; bhv[1] = bsh[tid + 256];
        blv[0] = bsl[tid]; blv[1] = bsl[tid + 256];
    };

    // ---- pack registers and store tiles into stage buffer ----
    auto store_tiles = [&](uint32_t bo) {
        #pragma unroll
        for (int j = 0; j < 2; ++j) {
            const int m = j * 32 + mg;
            uint32_t hp[4], lp[4];
            #pragma unroll
            for (int t = 0; t < 4; ++t) {
                hp[t] = prmt(av[j][2 * t], av[j][2 * t + 1], 0x7632u);
                lp[t] = prmt(av[j][2 * t], av[j][2 * t + 1], 0x5410u);
            }
            const uint32_t byte = (uint32_t)m * ROWB + (uint32_t)u8 * 16u;
            *(uint4*)(sm + bo + OFF_AH + byte) = *(uint4*)hp;
            *(uint4*)(sm + bo + OFF_AL + byte) = *(uint4*)lp;
        }
        const uint32_t d0 = (uint32_t)(tid >> 3) * ROWB + (uint32_t)(tid & 7) * 16u;
        const uint32_t e1 = tid + 256;
        const uint32_t d1 = (e1 >> 3) * ROWB + (e1 & 7) * 16u;
        *(uint4*)(sm + bo + OFF_BH + d0) = bhv[0];
        *(uint4*)(sm + bo + OFF_BH + d1) = bhv[1];
        *(uint4*)(sm + bo + OFF_BL + d0) = blv[0];
        *(uint4*)(sm + bo + OFF_BL + d1) = blv[1];
    };

    __syncthreads();            // raw/lut staged
    gather(0);
    store_tiles(0u);
    __syncthreads();            // stage 0 ready

    for (int c = 0; c < NCHUNK; ++c) {
        const uint32_t bo = (uint32_t)(c & 1) * STAGE_BYTES;
        const uint32_t bn = (uint32_t)((c + 1) & 1) * STAGE_BYTES;

        if (c < NCHUNK - 1) gather(c + 1);   // long-latency loads issued first

        // ---- MMA chunk c (overlaps gather latency) ----
        #pragma unroll
        for (int ks = 0; ks < 4; ++ks) {
            const uint32_t ko = (uint32_t)ks * 32u;
            uint32_t ah[4], al[4], bh[8], bl[8];
            ldmx4(ah, aA + bo + OFF_AH + ko);
            ldmx4(al, aA + bo + OFF_AL + ko);
            ldmx4(bh,     aB + bo + ko);
            ldmx4(bh + 4, aB + bo + 16u * ROWB + ko);
            ldmx4(bl,     aB + bo + (OFF_BL - OFF_BH) + ko);
            ldmx4(bl + 4, aB + bo + (OFF_BL - OFF_BH) + 16u * ROWB + ko);
            #pragma unroll
            for (int g = 0; g < 4; ++g) {
                mma_bf16(acc[g], ah, bh + 2 * g);
                mma_bf16(acc[g], ah, bl + 2 * g);
                mma_bf16(acc[g], al, bh + 2 * g);
            }
        }

        if (c < NCHUNK - 1) store_tiles(bn);
        __syncthreads();
    }

    // ---- epilogue: bias + store ----
    #pragma unroll
    for (int half = 0; half < 2; ++half) {
        const int gy = row0 + wm;
        const int gx = col0 + grp + half * 8;
        float* op = &out[((b * OUT_C) * HH + gy) * WW + gx];
        #pragma unroll
        for (int g = 0; g < 4; ++g) {
            const int n = wn * 32 + g * 8 + tid4 * 2;
            op[n * (HH * WW)]       = acc[g][half * 2]     + biass[n];
            op[(n + 1) * (HH * WW)] = acc[g][half * 2 + 1] + biass[n + 1];
        }
    }
}

extern "C" void kernel_launch(void* const* d_in, const int* in_sizes, int n_in,
                              void* d_out, int out_size)
{
    const float* x    = (const float*)d_in[0];
    const float* wgt  = (const float*)d_in[1];
    const float* bias = (const float*)d_in[2];
    float* out        = (float*)d_out;

    cudaFuncSetAttribute(conv3x3_hmma_kernel,
                         cudaFuncAttributeMaxDynamicSharedMemorySize, SMEM_BYTES);

    prep_weights_kernel<<<(NCHUNK * 64 * KCH + 255) / 256, 256>>>(wgt);

    dim3 grid(WW / TCOLS, HH / TROWS, NB);   // (7, 28, 2) = 392 CTAs
    conv3x3_hmma_kernel<<<grid, 256, SMEM_BYTES>>>(x, bias, out);
}

// round 7
// speedup vs baseline: 1.0035x; 1.0035x over previous
#include <cuda_runtime.h>
#include <cuda_bf16.h>
#include <cstdint>

#define IN_C  64
#define OUT_C 64
#define HH    112
#define WW    112
#define NB    2

#define TROWS 4
#define TCOLS 16
#define KTOT  576
#define KCH   64
#define NCHUNK 9

// raw tile: [row 6][col 18][ic 64] packed hi|lo uint32, run padded to 68
#define RAW_R 6
#define RAW_C 18
#define RUNPAD 68
#define RAW_PER_IC (RAW_R * RAW_C)      // 108 (logical)
#define RAW_U32 (RAW_R * RAW_C * RUNPAD) // 7344 uint32 = 29376 B

#define ROWB 144u        // 64 bf16 padded to 144 B per tile row

// smem layout
#define OFF_AH  0u
#define OFF_AL  9216u
#define OFF_BH  18432u
#define OFF_BL  27648u
#define OFF_RAW 36864u      // 29376 B
#define OFF_BIAS 66240u     // 256 B
#define SMEM_BYTES 66560u

// pre-permuted weights: [chunk(tap) 9][n 64][ic 64] bf16
__device__ __align__(16) __nv_bfloat16 Bh_g[NCHUNK * 64 * KCH];
__device__ __align__(16) __nv_bfloat16 Bl_g[NCHUNK * 64 * KCH];

__device__ __forceinline__ uint32_t smem_u32(const void* p) {
    uint32_t a;
    asm("{ .reg .u64 t; cvta.to.shared.u64 t, %1; cvt.u32.u64 %0, t; }" : "=r"(a) : "l"(p));
    return a;
}
__device__ __forceinline__ void mma_bf16(float* d, const uint32_t* a, const uint32_t* b) {
    asm volatile(
        "mma.sync.aligned.m16n8k16.row.col.f32.bf16.bf16.f32 "
        "{%0,%1,%2,%3}, {%4,%5,%6,%7}, {%8,%9}, {%0,%1,%2,%3};"
        : "+f"(d[0]), "+f"(d[1]), "+f"(d[2]), "+f"(d[3])
        : "r"(a[0]), "r"(a[1]), "r"(a[2]), "r"(a[3]), "r"(b[0]), "r"(b[1]));
}
__device__ __forceinline__ void ldmx4(uint32_t* r, uint32_t addr) {
    asm volatile("ldmatrix.sync.aligned.m8n8.x4.shared.b16 {%0,%1,%2,%3}, [%4];"
        : "=r"(r[0]), "=r"(r[1]), "=r"(r[2]), "=r"(r[3]) : "r"(addr));
}
__device__ __forceinline__ uint32_t prmt(uint32_t a, uint32_t b, uint32_t sel) {
    uint32_t d;
    asm("prmt.b32 %0, %1, %2, %3;" : "=r"(d) : "r"(a), "r"(b), "r"(sel));
    return d;
}

// ---- pre-kernel: split + permute weights to tap-major bf16 hi/lo ----
__global__ void __launch_bounds__(256)
prep_weights_kernel(const float* __restrict__ wgt)
{
    const int i = blockIdx.x * 256 + threadIdx.x;
    if (i >= NCHUNK * 64 * KCH) return;
    const int tap = i >> 12;
    const int n   = (i >> 6) & 63;
    const int ic  = i & 63;
    const float v = wgt[n * KTOT + ic * 9 + tap];
    const uint32_t u  = __float_as_uint(v);
    const uint32_t hu = u & 0xFFFF0000u;
    const float lo = v - __uint_as_float(hu);
    Bh_g[i] = __ushort_as_bfloat16((unsigned short)(hu >> 16));
    Bl_g[i] = __float2bfloat16_rn(lo);
}

// ---- main kernel: 128 threads, 4 warps of 32m x 32n ----
__global__ void __launch_bounds__(128, 3)
conv3x3_hmma_kernel(const float* __restrict__ x,
                    const float* __restrict__ bias,
                    float* __restrict__ out)
{
    extern __shared__ char sm[];
    const uint32_t sb = smem_u32(sm);

    const int tid  = threadIdx.x;
    const int wid  = tid >> 5;
    const int lane = tid & 31;
    const int grp  = lane >> 2;
    const int tid4 = lane & 3;

    const int wm = wid & 1;         // 2 m-groups of 32
    const int wn = wid >> 1;        // 2 n-groups of 32

    const int col0 = blockIdx.x * TCOLS;
    const int row0 = blockIdx.y * TROWS;
    const int b    = blockIdx.z;

    uint32_t* rawp  = (uint32_t*)(sm + OFF_RAW);
    float*    biass = (float*)(sm + OFF_BIAS);

    // ---- stage raw x tile: [r][c][ic], packed (hi16|lo16), run pad 68 ----
    for (int e = tid; e < IN_C * RAW_PER_IC; e += 128) {
        const int ic  = e / RAW_PER_IC;
        const int rem = e - ic * RAW_PER_IC;
        const int r   = rem / RAW_C;
        const int c   = rem - r * RAW_C;
        const int gr  = row0 - 1 + r;
        const int gc  = col0 - 1 + c;
        float v = 0.0f;
        if ((unsigned)gr < (unsigned)HH && (unsigned)gc < (unsigned)WW)
            v = x[(((b * IN_C) + ic) * HH + gr) * WW + gc];
        const uint32_t u  = __float_as_uint(v);
        const uint32_t hu = u & 0xFFFF0000u;
        const float lo = v - __uint_as_float(hu);
        rawp[(r * RAW_C + c) * RUNPAD + ic] =
            hu | (uint32_t)__bfloat16_as_ushort(__float2bfloat16_rn(lo));
    }
    if (tid < OUT_C) biass[tid] = bias[tid];

    float acc[2][4][4];
    #pragma unroll
    for (int f = 0; f < 2; ++f)
        #pragma unroll
        for (int g = 0; g < 4; ++g)
            #pragma unroll
            for (int q = 0; q < 4; ++q) acc[f][g][q] = 0.0f;

    // A-build mapping: thread owns row m = tid&63, half h2 = tid>>6 (32 ic each)
    const int am = tid & 63;
    const int h2 = tid >> 6;
    const int rm = am >> 4;
    const int cm = am & 15;
    const uint32_t aStoreH = (uint32_t)am * ROWB + (uint32_t)h2 * 64u;

    // ldmatrix per-lane base addresses
    const int matq = lane >> 3;
    const int rq   = lane & 7;
    const uint32_t aA = sb
        + (uint32_t)(wm * 32 + ((matq & 1) << 3) + rq) * ROWB
        + (uint32_t)((matq >> 1) << 4);
    const uint32_t aB = sb + OFF_BH
        + (uint32_t)(wn * 32 + ((matq >> 1) << 3) + rq) * ROWB
        + (uint32_t)((matq & 1) << 4);

    // B prefetch registers (chunk ahead)
    uint4 bh4[4], bl4[4];
    auto ldB = [&](int chunk) {
        const uint4* bsh = ((const uint4*)Bh_g) + chunk * 512 + tid * 4;
        const uint4* bsl = ((const uint4*)Bl_g) + chunk * 512 + tid * 4;
        #pragma unroll
        for (int i = 0; i < 4; ++i) { bh4[i] = bsh[i]; bl4[i] = bsl[i]; }
    };

    __syncthreads();            // raw staged
    ldB(0);

    for (int c = 0; c < NCHUNK; ++c) {
        if (c > 0) __syncthreads();   // previous MMA done reading tiles

        // ---- store B tiles from prefetch regs ----
        #pragma unroll
        for (int i = 0; i < 4; ++i) {
            const uint32_t e   = (uint32_t)tid * 4u + i;
            const uint32_t dst = (e >> 3) * ROWB + (e & 7) * 16u;
            *(uint4*)(sm + OFF_BH + dst) = bh4[i];
            *(uint4*)(sm + OFF_BL + dst) = bl4[i];
        }

        // ---- build A tile for tap c: contiguous 128B copy + split ----
        {
            const int dy = c / 3, dx = c - dy * 3;
            const uint32_t* src = rawp + ((rm + dy) * RAW_C + cm + dx) * RUNPAD + h2 * 32;
            #pragma unroll
            for (int j = 0; j < 8; j += 2) {
                const uint4 a0 = *(const uint4*)(src + j * 4);
                const uint4 a1 = *(const uint4*)(src + j * 4 + 4);
                uint4 h, l;
                h.x = prmt(a0.x, a0.y, 0x7632u); h.y = prmt(a0.z, a0.w, 0x7632u);
                h.z = prmt(a1.x, a1.y, 0x7632u); h.w = prmt(a1.z, a1.w, 0x7632u);
                l.x = prmt(a0.x, a0.y, 0x5410u); l.y = prmt(a0.z, a0.w, 0x5410u);
                l.z = prmt(a1.x, a1.y, 0x5410u); l.w = prmt(a1.z, a1.w, 0x5410u);
                const uint32_t dst = aStoreH + (uint32_t)(j >> 1) * 16u;
                *(uint4*)(sm + OFF_AH + dst) = h;
                *(uint4*)(sm + OFF_AL + dst) = l;
            }
        }

        if (c < NCHUNK - 1) ldB(c + 1);   // hide LDG under MMA

        __syncthreads();

        // ---- MMA: 4 k16-steps, 3 passes, 32x32 warp tile ----
        #pragma unroll
        for (int ks = 0; ks < 4; ++ks) {
            const uint32_t ko = (uint32_t)ks * 32u;
            uint32_t ah[2][4], al[2][4], bh[8], bl[8];
            ldmx4(ah[0], aA + OFF_AH + ko);
            ldmx4(ah[1], aA + OFF_AH + 16u * ROWB + ko);
            ldmx4(al[0], aA + OFF_AL + ko);
            ldmx4(al[1], aA + OFF_AL + 16u * ROWB + ko);
            ldmx4(bh,     aB + ko);
            ldmx4(bh + 4, aB + 16u * ROWB + ko);
            ldmx4(bl,     aB + (OFF_BL - OFF_BH) + ko);
            ldmx4(bl + 4, aB + (OFF_BL - OFF_BH) + 16u * ROWB + ko);
            #pragma unroll
            for (int f = 0; f < 2; ++f)
                #pragma unroll
                for (int g = 0; g < 4; ++g) {
                    mma_bf16(acc[f][g], ah[f], bh + 2 * g);
                    mma_bf16(acc[f][g], ah[f], bl + 2 * g);
                    mma_bf16(acc[f][g], al[f], bh + 2 * g);
                }
        }
    }

    // ---- epilogue: bias + store ----
    #pragma unroll
    for (int f = 0; f < 2; ++f) {
        #pragma unroll
        for (int half = 0; half < 2; ++half) {
            const int m  = wm * 32 + f * 16 + half * 8 + grp;
            const int gy = row0 + (m >> 4);
            const int gx = col0 + (m & 15);
            float* op = &out[((b * OUT_C) * HH + gy) * WW + gx];
            #pragma unroll
            for (int g = 0; g < 4; ++g) {
                const int n = wn * 32 + g * 8 + tid4 * 2;
                op[n * (HH * WW)]       = acc[f][g][half * 2]     + biass[n];
                op[(n + 1) * (HH * WW)] = acc[f][g][half * 2 + 1] + biass[n + 1];
            }
        }
    }
}

extern "C" void kernel_launch(void* const* d_in, const int* in_sizes, int n_in,
                              void* d_out, int out_size)
{
    const float* x    = (const float*)d_in[0];
    const float* wgt  = (const float*)d_in[1];
    const float* bias = (const float*)d_in[2];
    float* out        = (float*)d_out;

    cudaFuncSetAttribute(conv3x3_hmma_kernel,
                         cudaFuncAttributeMaxDynamicSharedMemorySize, SMEM_BYTES);

    prep_weights_kernel<<<(NCHUNK * 64 * KCH + 255) / 256, 256>>>(wgt);

    dim3 grid(WW / TCOLS, HH / TROWS, NB);   // (7, 28, 2) = 392 CTAs
    conv3x3_hmma_kernel<<<grid, 128, SMEM_BYTES>>>(x, bias, out);
}

// round 8
// speedup vs baseline: 1.4510x; 1.4460x over previous
#include <cuda_runtime.h>
#include <cstdint>

#define IN_C  64
#define OUT_C 64
#define HH    112
#define WW    112
#define NB    2

#define TROWS 4
#define TCOLS 16
#define KTOT  576
#define NTAP  9

// raw planes: [window 108][ic 64] int8, row stride 80 B
#define RAW_WIN 108
#define RAW_STRIDE 80

// concat tiles: 64 rows x 128 int8, stride 144 B
#define TSTRIDE 144u

// smem offsets
#define OFF_AC   0u          // 64*144 = 9216
#define OFF_BC   9216u       // 9216
#define OFF_RAW1 18432u      // 8640
#define OFF_RAW2 27072u      // 8640
#define OFF_BIAS 35712u      // 256
#define SMEM_BYTES 35968u

// quantization scales
#define SX1 24.0f
#define SX2 6144.0f          /* 24*256  */
#define SW1 512.0f
#define SW2 131072.0f        /* 512*256 */
#define C1F (1.0f/12288.0f)      /* 1/(24*512)   */
#define C2F (1.0f/3145728.0f)    /* 1/(24*512*256) */

// pre-quantized weights, concat layout: [tap 9][n 64][ w2(64B) | w1(64B) | pad 16 ]
__device__ __align__(16) int8_t BC_g[NTAP * 64 * TSTRIDE];

__device__ __forceinline__ uint32_t smem_u32(const void* p) {
    uint32_t a;
    asm("{ .reg .u64 t; cvta.to.shared.u64 t, %1; cvt.u32.u64 %0, t; }" : "=r"(a) : "l"(p));
    return a;
}
__device__ __forceinline__ void mma_s8(int* d, const uint32_t* a, const uint32_t* b) {
    asm volatile(
        "mma.sync.aligned.m16n8k32.row.col.s32.s8.s8.s32 "
        "{%0,%1,%2,%3}, {%4,%5,%6,%7}, {%8,%9}, {%0,%1,%2,%3};"
        : "+r"(d[0]), "+r"(d[1]), "+r"(d[2]), "+r"(d[3])
        : "r"(a[0]), "r"(a[1]), "r"(a[2]), "r"(a[3]), "r"(b[0]), "r"(b[1]));
}
__device__ __forceinline__ void ldmx4(uint32_t* r, uint32_t addr) {
    asm volatile("ldmatrix.sync.aligned.m8n8.x4.shared.b16 {%0,%1,%2,%3}, [%4];"
        : "=r"(r[0]), "=r"(r[1]), "=r"(r[2]), "=r"(r[3]) : "r"(addr));
}
__device__ __forceinline__ int clampi(int v) { return max(-127, min(127, v)); }

// ---- pre-kernel: quantize weights to int8 (w1, w2) in concat layout ----
__global__ void __launch_bounds__(256)
prep_weights_kernel(const float* __restrict__ wgt)
{
    const int i = blockIdx.x * 256 + threadIdx.x;
    if (i >= NTAP * 64 * 64) return;
    const int tap = i >> 12;
    const int n   = (i >> 6) & 63;
    const int ic  = i & 63;
    const float w = wgt[n * KTOT + ic * 9 + tap];
    int w1 = clampi(__float2int_rn(w * SW1));
    const float rw = w - (float)w1 * (1.0f / SW1);
    int w2 = clampi(__float2int_rn(rw * SW2));
    int8_t* row = BC_g + (tap * 64 + n) * TSTRIDE;
    row[ic]      = (int8_t)w2;   // cross left half
    row[64 + ic] = (int8_t)w1;   // cross right half == main-pass B
}

// ---- main kernel: 128 threads, 4 warps of 32m x 32n ----
__global__ void __launch_bounds__(128, 4)
conv3x3_i8_kernel(const float* __restrict__ x,
                  const float* __restrict__ bias,
                  float* __restrict__ out)
{
    extern __shared__ char sm[];
    const uint32_t sb = smem_u32(sm);

    const int tid  = threadIdx.x;
    const int wid  = tid >> 5;
    const int lane = tid & 31;
    const int grp  = lane >> 2;
    const int tid4 = lane & 3;

    const int wm = wid & 1;         // 2 m-groups of 32
    const int wn = wid >> 1;        // 2 n-groups of 32

    const int col0 = blockIdx.x * TCOLS;
    const int row0 = blockIdx.y * TROWS;
    const int b    = blockIdx.z;

    float* biass = (float*)(sm + OFF_BIAS);

    // ---- stage raw x, quantized to two int8 planes ----
    // e mapping: ic = e / 108, window = e % 108  (coalesced gc runs)
    for (int e = tid; e < IN_C * RAW_WIN; e += 128) {
        const int ic  = e / RAW_WIN;
        const int wdw = e - ic * RAW_WIN;
        const int r   = wdw / 18;
        const int c   = wdw - r * 18;
        const int gr  = row0 - 1 + r;
        const int gc  = col0 - 1 + c;
        float v = 0.0f;
        if ((unsigned)gr < (unsigned)HH && (unsigned)gc < (unsigned)WW)
            v = x[(((b * IN_C) + ic) * HH + gr) * WW + gc];
        int x1 = clampi(__float2int_rn(v * SX1));
        const float rx = v - (float)x1 * (1.0f / SX1);
        int x2 = clampi(__float2int_rn(rx * SX2));
        ((int8_t*)(sm + OFF_RAW1))[wdw * RAW_STRIDE + ic] = (int8_t)x1;
        ((int8_t*)(sm + OFF_RAW2))[wdw * RAW_STRIDE + ic] = (int8_t)x2;
    }
    if (tid < OUT_C) biass[tid] = bias[tid];

    // accumulators: acc1 = x1*w1 (scale 12288), acc2 = cross (scale 3145728)
    int acc1[2][4][4], acc2[2][4][4];
    #pragma unroll
    for (int f = 0; f < 2; ++f)
        #pragma unroll
        for (int g = 0; g < 4; ++g)
            #pragma unroll
            for (int q = 0; q < 4; ++q) { acc1[f][g][q] = 0; acc2[f][g][q] = 0; }

    // A-build mapping: thread owns row m = tid&63, plane p = tid>>6
    const int am = tid & 63;
    const int pl = tid >> 6;
    const int wb = (am >> 4) * 18 + (am & 15);   // window base for this row
    const uint32_t rawOff = pl ? OFF_RAW2 : OFF_RAW1;
    const uint32_t aDst   = OFF_AC + (uint32_t)am * TSTRIDE + (uint32_t)pl * 64u;

    // ldmatrix per-lane base addresses
    const int q  = lane >> 3;
    const int rq = lane & 7;
    const uint32_t aA = sb + OFF_AC
        + (uint32_t)(wm * 32 + ((q & 1) << 3) + rq) * TSTRIDE
        + (uint32_t)((q >> 1) << 4);
    const uint32_t aB = sb + OFF_BC
        + (uint32_t)(wn * 32 + ((q >> 1) << 3) + rq) * TSTRIDE
        + (uint32_t)((q & 1) << 4);

    __syncthreads();            // raw planes staged

    for (int tap = 0; tap < NTAP; ++tap) {
        if (tap > 0) __syncthreads();     // previous MMA done reading tiles

        // ---- build A concat tile: row m = [a1 (64B) | a2 (64B)] ----
        {
            const int dy = tap / 3, dx = tap - dy * 3;
            const uint32_t src = rawOff + (uint32_t)(wb + dy * 18 + dx) * RAW_STRIDE;
            #pragma unroll
            for (int i = 0; i < 4; ++i)
                *(uint4*)(sm + aDst + i * 16) = *(const uint4*)(sm + src + i * 16);
        }
        // ---- copy B concat tile (9216 B) ----
        {
            const uint4* gBC = (const uint4*)(BC_g + tap * 64 * TSTRIDE);
            uint4* sBC = (uint4*)(sm + OFF_BC);
            #pragma unroll
            for (int i = tid; i < 576; i += 128) sBC[i] = gBC[i];
        }
        __syncthreads();

        // ---- MMA: cross over ks 0..3 into acc2; main (a1*w1) reuses
        //      A[ks<2] with B[ks+2] into acc1 ----
        uint32_t B2[8], B3[8];
        ldmx4(B2,     aB + 2 * 32);
        ldmx4(B2 + 4, aB + 16u * TSTRIDE + 2 * 32);
        ldmx4(B3,     aB + 3 * 32);
        ldmx4(B3 + 4, aB + 16u * TSTRIDE + 3 * 32);

        // ks = 2, 3 (cross only, B already loaded)
        #pragma unroll
        for (int ks = 2; ks < 4; ++ks) {
            uint32_t A0[4], A1[4];
            ldmx4(A0, aA + ks * 32);
            ldmx4(A1, aA + 16u * TSTRIDE + ks * 32);
            uint32_t* Bk = (ks == 2) ? B2 : B3;
            #pragma unroll
            for (int g = 0; g < 4; ++g) {
                mma_s8(acc2[0][g], A0, Bk + 2 * g);
                mma_s8(acc2[1][g], A1, Bk + 2 * g);
            }
        }
        // ks = 0, 1: cross with fresh B[ks], main with retained B[ks+2]
        #pragma unroll
        for (int ks = 0; ks < 2; ++ks) {
            uint32_t A0[4], A1[4], Bk[8];
            ldmx4(A0, aA + ks * 32);
            ldmx4(A1, aA + 16u * TSTRIDE + ks * 32);
            ldmx4(Bk,     aB + ks * 32);
            ldmx4(Bk + 4, aB + 16u * TSTRIDE + ks * 32);
            uint32_t* Bm = (ks == 0) ? B2 : B3;
            #pragma unroll
            for (int g = 0; g < 4; ++g) {
                mma_s8(acc2[0][g], A0, Bk + 2 * g);
                mma_s8(acc2[1][g], A1, Bk + 2 * g);
                mma_s8(acc1[0][g], A0, Bm + 2 * g);
                mma_s8(acc1[1][g], A1, Bm + 2 * g);
            }
        }
    }

    // ---- epilogue: reconstruct fp32, add bias, store ----
    #pragma unroll
    for (int f = 0; f < 2; ++f) {
        #pragma unroll
        for (int half = 0; half < 2; ++half) {
            const int m  = wm * 32 + f * 16 + half * 8 + grp;
            const int gy = row0 + (m >> 4);
            const int gx = col0 + (m & 15);
            float* op = &out[((b * OUT_C) * HH + gy) * WW + gx];
            #pragma unroll
            for (int g = 0; g < 4; ++g) {
                const int n = wn * 32 + g * 8 + tid4 * 2;
                const float v0 = (float)acc1[f][g][half * 2]     * C1F
                               + (float)acc2[f][g][half * 2]     * C2F + biass[n];
                const float v1 = (float)acc1[f][g][half * 2 + 1] * C1F
                               + (float)acc2[f][g][half * 2 + 1] * C2F + biass[n + 1];
                op[n * (HH * WW)]       = v0;
                op[(n + 1) * (HH * WW)] = v1;
            }
        }
    }
}

extern "C" void kernel_launch(void* const* d_in, const int* in_sizes, int n_in,
                              void* d_out, int out_size)
{
    const float* x    = (const float*)d_in[0];
    const float* wgt  = (const float*)d_in[1];
    const float* bias = (const float*)d_in[2];
    float* out        = (float*)d_out;

    cudaFuncSetAttribute(conv3x3_i8_kernel,
                         cudaFuncAttributeMaxDynamicSharedMemorySize, SMEM_BYTES);

    prep_weights_kernel<<<(NTAP * 64 * 64 + 255) / 256, 256>>>(wgt);

    dim3 grid(WW / TCOLS, HH / TROWS, NB);   // (7, 28, 2) = 392 CTAs
    conv3x3_i8_kernel<<<grid, 128, SMEM_BYTES>>>(x, bias, out);
}